// round 9
// baseline (speedup 1.0000x reference)
#include <cuda_runtime.h>

// Cox partial-likelihood loss, n = 8192, sort + suffix-scan algorithm.
// loss = -mean_i[ (theta_i - log(sum_{j: t_j>=t_i} exp(theta_j) + eps)) * e_i ]
//
// Key identity: S_i = sum_{j: t_j >= t_i} exp(theta_j) is a suffix sum over
// t-sorted order. So:
//   K1: 16 blocks sort their 512-chunk of (t, exp(risk)) ascending by t
//       (bitonic network -> deterministic), suffix-scan exp, store
//       sorted-t + suffix arrays (with 0 sentinel at index 512).
//   K2: per i, S_i = sum over 16 chunks of suffix[lower_bound(t_i)]
//       (branchless binary search in smem, 16 independent searches -> MLP).
//       Then loss term, fixed-order block reduce, last-block election does
//       the final fixed-order sum, writes -sum/n, resets the counter.
//
// O(n log n)-ish instead of O(n^2): ~50x less work than the pair kernel.
// No device allocations, no fp atomics, graph-capturable, deterministic.

#define N        8192
#define CHUNK    512
#define NCHUNK   16          // N / CHUNK
#define K1_BLOCK 512
#define K2_BLOCK 128
#define K2_GRID  64          // N / K2_BLOCK
#define EPS_F    1e-8f

__device__ float g_tsorted[N];                  // chunk-sorted t
__device__ float g_sfx[NCHUNK * (CHUNK + 1)];   // suffix sums + sentinel
__device__ float g_bsum[K2_GRID];
__device__ int   g_done;                        // zero-init

// ---------------------------------------------------------------- K1
__global__ __launch_bounds__(K1_BLOCK) void cox_sort_kernel(
    const float* __restrict__ risk,
    const float* __restrict__ t)
{
    __shared__ float ks[CHUNK];   // keys: t
    __shared__ float vs[CHUNK];   // payload: exp(risk)
    __shared__ float sf[CHUNK];   // suffix scan

    const int tid  = threadIdx.x;
    const int base = blockIdx.x * CHUNK;

    ks[tid] = t[base + tid];
    vs[tid] = expf(risk[base + tid]);
    __syncthreads();

    // bitonic sort ascending (data-independent network -> deterministic)
    for (int k = 2; k <= CHUNK; k <<= 1) {
        for (int j = k >> 1; j > 0; j >>= 1) {
            const int ixj = tid ^ j;
            if (ixj > tid) {
                const bool up = ((tid & k) == 0);
                const float a = ks[tid], b = ks[ixj];
                if ((a > b) == up) {
                    ks[tid] = b; ks[ixj] = a;
                    const float va = vs[tid], vb = vs[ixj];
                    vs[tid] = vb; vs[ixj] = va;
                }
            }
            __syncthreads();
        }
    }

    // inclusive suffix scan of vs -> sf  (Hillis-Steele, reversed)
    sf[tid] = vs[tid];
    __syncthreads();
    for (int off = 1; off < CHUNK; off <<= 1) {
        const float add = (tid + off < CHUNK) ? sf[tid + off] : 0.0f;
        __syncthreads();
        sf[tid] += add;
        __syncthreads();
    }

    g_tsorted[base + tid] = ks[tid];
    g_sfx[blockIdx.x * (CHUNK + 1) + tid] = sf[tid];
    if (tid == 0)
        g_sfx[blockIdx.x * (CHUNK + 1) + CHUNK] = 0.0f;   // sentinel
}

// ---------------------------------------------------------------- K2
__global__ __launch_bounds__(K2_BLOCK) void cox_loss_kernel(
    const float* __restrict__ risk,
    const float* __restrict__ t,
    const float* __restrict__ e,
    float* __restrict__ out,
    int n)
{
    __shared__ float ts[N];              // 32 KB: all sorted chunks
    __shared__ float red[K2_BLOCK];

    const int tid = threadIdx.x;

    // stage all sorted-t chunks (coalesced)
    for (int idx = tid; idx < N; idx += K2_BLOCK)
        ts[idx] = g_tsorted[idx];
    __syncthreads();

    const int   i  = blockIdx.x * K2_BLOCK + tid;
    const float ti = t[i];

    // 16 independent branchless binary searches:
    // pos[c] = # elements in chunk c with t < ti  (lower_bound)
    int pos[NCHUNK];
#pragma unroll
    for (int c = 0; c < NCHUNK; c++) pos[c] = 0;

#pragma unroll
    for (int bit = CHUNK >> 1; bit > 0; bit >>= 1) {
#pragma unroll
        for (int c = 0; c < NCHUNK; c++)
            if (ts[c * CHUNK + pos[c] + bit - 1] < ti) pos[c] += bit;
    }
#pragma unroll
    for (int c = 0; c < NCHUNK; c++)            // allow pos == CHUNK
        if (ts[c * CHUNK + pos[c]] < ti) pos[c]++;

    // S_i = sum of suffix values (fixed chunk order)
    float S = 0.0f;
#pragma unroll
    for (int c = 0; c < NCHUNK; c++)
        S += g_sfx[c * (CHUNK + 1) + pos[c]];

    float acc = (risk[i] - logf(S + EPS_F)) * e[i];

    // fixed-order block reduction (128 values)
    red[tid] = acc;
    __syncthreads();
    if (tid < 64) red[tid] += red[tid + 64];
    __syncthreads();
    if (tid < 32) {
        float v = red[tid] + red[tid + 32];
#pragma unroll
        for (int off = 16; off > 0; off >>= 1)
            v += __shfl_down_sync(0xffffffffu, v, off);

        if (tid == 0) {
            g_bsum[blockIdx.x] = v;
            __threadfence();
            if (atomicAdd(&g_done, 1) == K2_GRID - 1) {
                __threadfence();
                float total = 0.0f;
                for (int b = 0; b < K2_GRID; b++)     // fixed order
                    total += __ldcg(&g_bsum[b]);
                out[0] = -total / (float)n;
                g_done = 0;                            // reset for replay
                __threadfence();
            }
        }
    }
}

// ---------------------------------------------------------------- launch
extern "C" void kernel_launch(void* const* d_in, const int* in_sizes, int n_in,
                              void* d_out, int out_size) {
    const float* risk = (const float*)d_in[0];
    const float* t    = (const float*)d_in[1];
    const float* e    = (const float*)d_in[2];
    float* out = (float*)d_out;

    const int n = in_sizes[0];   // 8192

    cox_sort_kernel<<<NCHUNK, K1_BLOCK>>>(risk, t);
    cox_loss_kernel<<<K2_GRID, K2_BLOCK>>>(risk, t, e, out, n);
}

// round 10
// speedup vs baseline: 1.4168x; 1.4168x over previous
#include <cuda_runtime.h>

// Cox partial-likelihood loss, n = 8192, sort + suffix-scan algorithm.
// loss = -mean_i[ (theta_i - log(sum_{j: t_j>=t_i} exp(theta_j) + eps)) * e_i ]
//
// S_i = sum_{j: t_j >= t_i} exp(theta_j) is a suffix sum over t-sorted order.
//
// K1 (16 blocks x 512): hybrid bitonic sort of each 512-chunk of
//     (t, exp(risk)) -- j<32 stages via register shfl_xor (no barriers),
//     j>=32 stages via smem (20 barriers total vs 45) -- then a warp-shuffle
//     suffix scan (+1 cross-warp fixup). Stores sorted-t and suffix(+0
//     sentinel) per chunk. Fixed comparator network -> deterministic.
//
// K2 (grid 16x32, 256 thr): thread = one (i, chunk) pair. Stages the 2KB
//     sorted-t chunk + 2KB suffix table in smem, does ONE 10-step branchless
//     lower_bound, writes partial S contribution. Election: last of the 16
//     chunk-blocks per i-tile sums the 16 partials per i in fixed order,
//     applies log/event mask, block-reduces; global election sums 32 tile
//     sums in fixed order, writes -sum/n, resets counters for graph replay.
//
// No device allocations, no fp atomics, graph-capturable, deterministic.

#define N        8192
#define CHUNK    512
#define NCHUNK   16            // N / CHUNK
#define K1_BLOCK 512
#define K2_BLOCK 256
#define NTILE    32            // N / K2_BLOCK
#define EPS_F    1e-8f

__device__ float g_tsorted[N];                    // chunk-sorted t
__device__ float g_sfx[NCHUNK * (CHUNK + 1)];     // suffix sums + sentinel
__device__ float g_partS[NCHUNK * N];             // [chunk][i] partials
__device__ float g_bsum[NTILE];
__device__ int   g_done_it[NTILE];                // zero-init
__device__ int   g_done_final;                    // zero-init

// in-warp bitonic compare-exchange stage (j < 32)
__device__ __forceinline__ void bstage_shfl(float& key, float& val,
                                            int j, int k, int tid) {
    const float bk = __shfl_xor_sync(0xffffffffu, key, j);
    const float bv = __shfl_xor_sync(0xffffffffu, val, j);
    const bool lower = (tid & j) == 0;
    const bool up    = (tid & k) == 0;
    const bool take_b = (up == lower) ? (bk < key) : (bk > key);
    if (take_b) { key = bk; val = bv; }
}

// ---------------------------------------------------------------- K1
__global__ __launch_bounds__(K1_BLOCK) void cox_sort_kernel(
    const float* __restrict__ risk,
    const float* __restrict__ t)
{
    __shared__ float sk[CHUNK];
    __shared__ float sv[CHUNK];
    __shared__ float wsum[K1_BLOCK / 32];

    const int tid  = threadIdx.x;
    const int lane = tid & 31;
    const int w    = tid >> 5;
    const int base = blockIdx.x * CHUNK;

    float key = t[base + tid];
    float val = expf(risk[base + tid]);

    // phases k = 2..32: entirely in registers (15 shfl stages, no barriers)
#pragma unroll
    for (int k = 2; k <= 32; k <<= 1)
#pragma unroll
        for (int j = k >> 1; j >= 1; j >>= 1)
            bstage_shfl(key, val, j, k, tid);

    // phases k = 64..512: j>=32 via smem, j<32 via shfl
    for (int k = 64; k <= CHUNK; k <<= 1) {
        for (int j = k >> 1; j >= 32; j >>= 1) {
            sk[tid] = key; sv[tid] = val;
            __syncthreads();
            const int p = tid ^ j;
            const float bk = sk[p], bv = sv[p];
            const bool lower = (tid & j) == 0;
            const bool up    = (tid & k) == 0;
            const bool take_b = (up == lower) ? (bk < key) : (bk > key);
            if (take_b) { key = bk; val = bv; }
            __syncthreads();
        }
#pragma unroll
        for (int j = 16; j >= 1; j >>= 1)
            bstage_shfl(key, val, j, k, tid);
    }
    // registers now hold ascending-sorted (key = t, val = exp) at position tid

    // inclusive suffix scan of val: warp shfl scan + cross-warp fixup
    float v = val;
#pragma unroll
    for (int off = 1; off < 32; off <<= 1) {
        const float x = __shfl_down_sync(0xffffffffu, v, off);
        if (lane + off < 32) v += x;
    }
    if (lane == 0) wsum[w] = v;          // warp total (suffix at lane 0)
    __syncthreads();
    float add = 0.0f;
    for (int ww = w + 1; ww < K1_BLOCK / 32; ww++)   // fixed order, broadcast
        add += wsum[ww];
    v += add;

    g_tsorted[base + tid] = key;
    g_sfx[blockIdx.x * (CHUNK + 1) + tid] = v;
    if (tid == 0)
        g_sfx[blockIdx.x * (CHUNK + 1) + CHUNK] = 0.0f;   // sentinel
}

// ---------------------------------------------------------------- K2
__global__ __launch_bounds__(K2_BLOCK) void cox_search_kernel(
    const float* __restrict__ risk,
    const float* __restrict__ t,
    const float* __restrict__ e,
    float* __restrict__ out,
    int n)
{
    __shared__ float ts[CHUNK];
    __shared__ float sf[CHUNK + 1];
    __shared__ float red[K2_BLOCK];
    __shared__ int   flag;

    const int c   = blockIdx.x;     // chunk    0..15
    const int ib  = blockIdx.y;     // i-tile   0..31
    const int tid = threadIdx.x;

    // stage this chunk's sorted-t and suffix table (coalesced)
    for (int idx = tid; idx < CHUNK; idx += K2_BLOCK)
        ts[idx] = g_tsorted[c * CHUNK + idx];
    for (int idx = tid; idx < CHUNK + 1; idx += K2_BLOCK)
        sf[idx] = g_sfx[c * (CHUNK + 1) + idx];
    __syncthreads();

    const int   i  = ib * K2_BLOCK + tid;
    const float ti = t[i];

    // branchless lower_bound: pos = #elements in chunk with t < ti
    int pos = 0;
#pragma unroll
    for (int bit = CHUNK >> 1; bit >= 1; bit >>= 1)
        if (ts[pos + bit - 1] < ti) pos += bit;      // pos <= 511
    if (ts[pos] < ti) pos++;                          // allow pos == CHUNK

    g_partS[c * n + i] = sf[pos];                     // suffix contribution

    // ---- elect last chunk-block of this i-tile
    __threadfence();
    __syncthreads();
    if (tid == 0)
        flag = (atomicAdd(&g_done_it[ib], 1) == NCHUNK - 1);
    __syncthreads();
    if (!flag) return;

    __threadfence();   // acquire: all 16 partials for this tile visible

    // finalize: S_i = sum of 16 partials (fixed order, 16 independent LDGs)
    float S = 0.0f;
#pragma unroll
    for (int cc = 0; cc < NCHUNK; cc++)
        S += __ldcg(&g_partS[cc * n + i]);

    float acc = (risk[i] - logf(S + EPS_F)) * e[i];

    // fixed-order block reduction of 256 values
    red[tid] = acc;
    __syncthreads();
    if (tid < 128) red[tid] += red[tid + 128];
    __syncthreads();
    if (tid < 64)  red[tid] += red[tid + 64];
    __syncthreads();
    if (tid < 32) {
        float v = red[tid] + red[tid + 32];
#pragma unroll
        for (int off = 16; off > 0; off >>= 1)
            v += __shfl_down_sync(0xffffffffu, v, off);

        if (tid == 0) {
            g_bsum[ib] = v;
            __threadfence();
            if (atomicAdd(&g_done_final, 1) == NTILE - 1) {
                __threadfence();
                float total = 0.0f;
                for (int b = 0; b < NTILE; b++)       // fixed order
                    total += __ldcg(&g_bsum[b]);
                out[0] = -total / (float)n;

                // reset counters for next graph replay
                g_done_final = 0;
                for (int b = 0; b < NTILE; b++) g_done_it[b] = 0;
                __threadfence();
            }
        }
    }
}

// ---------------------------------------------------------------- launch
extern "C" void kernel_launch(void* const* d_in, const int* in_sizes, int n_in,
                              void* d_out, int out_size) {
    const float* risk = (const float*)d_in[0];
    const float* t    = (const float*)d_in[1];
    const float* e    = (const float*)d_in[2];
    float* out = (float*)d_out;

    const int n = in_sizes[0];   // 8192

    cox_sort_kernel<<<NCHUNK, K1_BLOCK>>>(risk, t);
    cox_search_kernel<<<dim3(NCHUNK, NTILE), K2_BLOCK>>>(risk, t, e, out, n);
}